// round 1
// baseline (speedup 1.0000x reference)
#include <cuda_runtime.h>
#include <cstdint>
#include <math.h>

// Problem dims
#define Bn  256
#define Tn  512
#define Fn  128
#define CUn 512
#define DUn 512
#define KX  640          // Fn + CUn
#define NG  2048         // 4*DUn
#define Rn  (Bn*Tn)      // 131072

// GEMM tiling
#define BM 128
#define BN 64
#define BK 32
#define ASTR 36          // As row stride (pad: 36 % 32 == 4 -> conflict-free frag loads)
#define BSTR 72          // Bs row stride (72 % 32 == 8 -> conflict-free frag loads)
#define ZSTR 68

// Scratch (static __device__ arrays: the sanctioned no-alloc workaround)
__device__ float g_Zpre[(size_t)Rn * NG];    // 1 GiB: x@W + b for all (t,b), rows r = t*256+b
__device__ float g_H[(size_t)Rn * DUn];      // 256 MB: h_t history, rows r = t*256+b
__device__ float g_hbuf[2][Bn * DUn];        // ping-pong h
__device__ float g_cbuf[Bn * DUn];           // c (in-place per (b,j), no races)

__device__ __forceinline__ uint32_t f2tf(float x){
    uint32_t r; asm("cvt.rna.tf32.f32 %0, %1;" : "=r"(r) : "f"(x)); return r;
}
__device__ __forceinline__ float tf2f(uint32_t u){ return __uint_as_float(u); }

__device__ __forceinline__ void st4_tf(float* dst, float4 v){
    dst[0]=tf2f(f2tf(v.x)); dst[1]=tf2f(f2tf(v.y));
    dst[2]=tf2f(f2tf(v.z)); dst[3]=tf2f(f2tf(v.w));
}

__device__ __forceinline__ void mma_tf32(float d[4],
        uint32_t a0, uint32_t a1, uint32_t a2, uint32_t a3,
        uint32_t b0, uint32_t b1){
    asm volatile(
        "mma.sync.aligned.m16n8k8.row.col.f32.tf32.tf32.f32 "
        "{%0,%1,%2,%3}, {%4,%5,%6,%7}, {%8,%9}, {%0,%1,%2,%3};\n"
        : "+f"(d[0]), "+f"(d[1]), "+f"(d[2]), "+f"(d[3])
        : "r"(a0), "r"(a1), "r"(a2), "r"(a3), "r"(b0), "r"(b1));
}

__device__ __forceinline__ float sigm(float x){ return 1.f/(1.f + __expf(-x)); }

// One BK-wide K-tile for the whole CTA (8 warps: 4 in M x 2 in N; warp tile 32x32)
__device__ __forceinline__ void compute_ktile(const float* As, const float* Bs,
                                              float acc[2][4][4], int wm, int wn, int lane){
    const int qr = lane >> 2, qc = lane & 3;
    #pragma unroll
    for (int k8 = 0; k8 < BK; k8 += 8){
        uint32_t a[2][4];
        #pragma unroll
        for (int mm = 0; mm < 2; mm++){
            const float* ap = As + (wm*32 + mm*16 + qr) * ASTR + k8 + qc;
            a[mm][0] = __float_as_uint(ap[0]);
            a[mm][1] = __float_as_uint(ap[8*ASTR]);
            a[mm][2] = __float_as_uint(ap[4]);
            a[mm][3] = __float_as_uint(ap[8*ASTR + 4]);
        }
        #pragma unroll
        for (int nn = 0; nn < 4; nn++){
            const float* bp = Bs + (k8 + qc) * BSTR + wn*32 + nn*8 + qr;
            uint32_t b0 = __float_as_uint(bp[0]);
            uint32_t b1 = __float_as_uint(bp[4*BSTR]);
            #pragma unroll
            for (int mm = 0; mm < 2; mm++)
                mma_tf32(acc[mm][nn], a[mm][0], a[mm][1], a[mm][2], a[mm][3], b0, b1);
        }
    }
}

// ---------------------------------------------------------------------------
// Zpre[t*256+b][n] = x_{b,t} @ W + bias   (x = [teacher_{t-1} (128) | conductor_t (512)])
// grid: (NG/BN = 32, Rn/BM = 1024); 128 rows per CTA -> constant t per CTA
// ---------------------------------------------------------------------------
__global__ __launch_bounds__(256) void k_pre(const float* __restrict__ teacher,
                                             const float* __restrict__ cond,
                                             const float* __restrict__ W,
                                             const float* __restrict__ bias){
    __shared__ float As[BM*ASTR];
    __shared__ float Bs[BK*BSTR];
    const int tid = threadIdx.x, lane = tid & 31, wid = tid >> 5;
    const int wm = wid & 3, wn = wid >> 2;
    const int n0 = blockIdx.x * BN;
    const int by = blockIdx.y;
    const int t  = by >> 1;            // 256 rows per t, 128 per CTA
    const int b0 = (by & 1) * BM;

    float acc[2][4][4];
    #pragma unroll
    for (int mm=0;mm<2;mm++)
        #pragma unroll
        for (int nn=0;nn<4;nn++)
            #pragma unroll
            for (int i=0;i<4;i++) acc[mm][nn][i]=0.f;

    for (int kt = 0; kt < KX/BK; kt++){     // 20 K-tiles; tiles 0-3 = teacher part
        int k0 = kt * BK;
        #pragma unroll
        for (int i = 0; i < 4; i++){
            int idx = tid + i*256;
            int row = idx >> 3, c4 = (idx & 7) * 4;
            int b  = b0 + row;
            int kg = k0 + c4;
            float4 v;
            if (kg < Fn){
                if (t == 0) v = make_float4(0.f,0.f,0.f,0.f);
                else v = *reinterpret_cast<const float4*>(
                            teacher + ((size_t)b*Tn + (t-1))*Fn + kg);
            } else {
                v = *reinterpret_cast<const float4*>(
                            cond + ((size_t)b*Tn + t)*CUn + (kg - Fn));
            }
            st4_tf(As + row*ASTR + c4, v);
        }
        #pragma unroll
        for (int i = 0; i < 2; i++){
            int idx = tid + i*256;
            int kr = idx >> 4, c4 = (idx & 15) * 4;
            float4 v = *reinterpret_cast<const float4*>(W + (size_t)(k0+kr)*NG + n0 + c4);
            st4_tf(Bs + kr*BSTR + c4, v);
        }
        __syncthreads();
        compute_ktile(As, Bs, acc, wm, wn, lane);
        __syncthreads();
    }

    const int qr = lane >> 2, qc = lane & 3;
    const size_t r0 = (size_t)by * BM;
    #pragma unroll
    for (int mm=0;mm<2;mm++){
        int row = wm*32 + mm*16 + qr;
        #pragma unroll
        for (int nn=0;nn<4;nn++){
            int col = n0 + wn*32 + nn*8 + qc*2;
            float bv0 = bias[col], bv1 = bias[col+1];
            float* z0 = g_Zpre + (r0 + row) * NG + col;
            z0[0] = acc[mm][nn][0] + bv0;
            z0[1] = acc[mm][nn][1] + bv1;
            float* z1 = g_Zpre + (r0 + row + 8) * NG + col;
            z1[0] = acc[mm][nn][2] + bv0;
            z1[1] = acc[mm][nn][3] + bv1;
        }
    }
}

// ---------------------------------------------------------------------------
// One recurrent step: z = Zpre[t] + h_{t-1}@U  -> gates -> c,h update.
// grid: (DUn/16 = 32 hidden tiles, Bn/BM = 2 batch tiles).
// CTA's 64 GEMM columns = 4 gate columns {q*512 + j0 + j} for its 16 hidden units.
// ---------------------------------------------------------------------------
__global__ __launch_bounds__(256) void k_step(const float* __restrict__ U, int t){
    __shared__ float smem[BM*ZSTR];            // 34816 B; As/Bs then reused as zs
    float* As = smem;
    float* Bs = smem + BM*ASTR;
    const int tid = threadIdx.x, lane = tid & 31, wid = tid >> 5;
    const int wm = wid & 3, wn = wid >> 2;
    const int j0 = blockIdx.x * 16;
    const int b0 = blockIdx.y * BM;
    const float* hprev = g_hbuf[t & 1];
    float* hnext = g_hbuf[(t + 1) & 1];

    float acc[2][4][4];
    #pragma unroll
    for (int mm=0;mm<2;mm++)
        #pragma unroll
        for (int nn=0;nn<4;nn++)
            #pragma unroll
            for (int i=0;i<4;i++) acc[mm][nn][i]=0.f;

    for (int kt = 0; kt < DUn/BK; kt++){     // 16 K-tiles
        int k0 = kt * BK;
        #pragma unroll
        for (int i = 0; i < 4; i++){
            int idx = tid + i*256;
            int row = idx >> 3, c4 = (idx & 7) * 4;
            float4 v = *reinterpret_cast<const float4*>(
                            hprev + (size_t)(b0+row)*DUn + k0 + c4);
            st4_tf(As + row*ASTR + c4, v);
        }
        #pragma unroll
        for (int i = 0; i < 2; i++){
            int idx = tid + i*256;
            int kr = idx >> 4, nl = (idx & 15) * 4;     // local col 0..60
            int q = nl >> 4, off = nl & 15;             // gate, unit offset
            float4 v = *reinterpret_cast<const float4*>(
                            U + (size_t)(k0+kr)*NG + q*DUn + j0 + off);
            st4_tf(Bs + kr*BSTR + nl, v);
        }
        __syncthreads();
        compute_ktile(As, Bs, acc, wm, wn, lane);
        __syncthreads();
    }

    // Stage z (acc + Zpre) into smem (safe: last compute already sync'ed)
    float* zs = smem;
    const int qr = lane >> 2, qc = lane & 3;
    #pragma unroll
    for (int mm=0;mm<2;mm++){
        int row = wm*32 + mm*16 + qr;
        size_t zr0 = ((size_t)t*Bn + b0 + row) * NG;
        size_t zr1 = ((size_t)t*Bn + b0 + row + 8) * NG;
        #pragma unroll
        for (int nn=0;nn<4;nn++){
            int colL = wn*32 + nn*8 + qc*2;             // 0..62, even
            int q = colL >> 4, j = colL & 15;
            size_t uc = (size_t)q*DUn + j0 + j;
            zs[row*ZSTR + colL]       = acc[mm][nn][0] + g_Zpre[zr0 + uc];
            zs[row*ZSTR + colL + 1]   = acc[mm][nn][1] + g_Zpre[zr0 + uc + 1];
            zs[(row+8)*ZSTR + colL]   = acc[mm][nn][2] + g_Zpre[zr1 + uc];
            zs[(row+8)*ZSTR + colL+1] = acc[mm][nn][3] + g_Zpre[zr1 + uc + 1];
        }
    }
    __syncthreads();

    // Gate phase: 128 rows x 16 units = 2048 items / 256 threads
    #pragma unroll
    for (int i = 0; i < 8; i++){
        int item = tid + i*256;
        int row = item >> 4, j = item & 15;
        int b  = b0 + row;
        int jg = j0 + j;
        float zi = zs[row*ZSTR + j];
        float zf = zs[row*ZSTR + 16 + j];
        float zg = zs[row*ZSTR + 32 + j];
        float zo = zs[row*ZSTR + 48 + j];
        float si = sigm(zi), sf = sigm(zf), so = sigm(zo);
        float tg = tanhf(zg);
        size_t ci = (size_t)b*DUn + jg;
        float c  = g_cbuf[ci];
        float cn = sf*c + si*tg;
        float hn = so * tanhf(cn);
        g_cbuf[ci] = cn;
        hnext[ci]  = hn;
        g_H[((size_t)t*Bn + b)*DUn + jg] = hn;
    }
}

// ---------------------------------------------------------------------------
// out[b,t,f] = sigmoid(H[t,b,:] @ Wo + bo)  ; grid: (Fn/BN = 2, Rn/BM = 1024)
// ---------------------------------------------------------------------------
__global__ __launch_bounds__(256) void k_out(const float* __restrict__ Wo,
                                             const float* __restrict__ bo,
                                             float* __restrict__ out){
    __shared__ float As[BM*ASTR];
    __shared__ float Bs[BK*BSTR];
    const int tid = threadIdx.x, lane = tid & 31, wid = tid >> 5;
    const int wm = wid & 3, wn = wid >> 2;
    const int f0 = blockIdx.x * BN;
    const int r0 = blockIdx.y * BM;

    float acc[2][4][4];
    #pragma unroll
    for (int mm=0;mm<2;mm++)
        #pragma unroll
        for (int nn=0;nn<4;nn++)
            #pragma unroll
            for (int i=0;i<4;i++) acc[mm][nn][i]=0.f;

    for (int kt = 0; kt < DUn/BK; kt++){
        int k0 = kt * BK;
        #pragma unroll
        for (int i = 0; i < 4; i++){
            int idx = tid + i*256;
            int row = idx >> 3, c4 = (idx & 7) * 4;
            float4 v = *reinterpret_cast<const float4*>(
                            g_H + (size_t)(r0+row)*DUn + k0 + c4);
            st4_tf(As + row*ASTR + c4, v);
        }
        #pragma unroll
        for (int i = 0; i < 2; i++){
            int idx = tid + i*256;
            int kr = idx >> 4, c4 = (idx & 15) * 4;
            float4 v = *reinterpret_cast<const float4*>(
                            Wo + (size_t)(k0+kr)*Fn + f0 + c4);
            st4_tf(Bs + kr*BSTR + c4, v);
        }
        __syncthreads();
        compute_ktile(As, Bs, acc, wm, wn, lane);
        __syncthreads();
    }

    const int qr = lane >> 2, qc = lane & 3;
    #pragma unroll
    for (int mm=0;mm<2;mm++){
        int r = r0 + wm*32 + mm*16 + qr;
        #pragma unroll
        for (int nn=0;nn<4;nn++){
            int f = f0 + wn*32 + nn*8 + qc*2;
            float bv0 = bo[f], bv1 = bo[f+1];
            {
                int b = r & (Bn-1), tt = r >> 8;
                float* o = out + ((size_t)b*Tn + tt)*Fn + f;
                o[0] = sigm(acc[mm][nn][0] + bv0);
                o[1] = sigm(acc[mm][nn][1] + bv1);
            }
            {
                int r2 = r + 8;
                int b = r2 & (Bn-1), tt = r2 >> 8;
                float* o = out + ((size_t)b*Tn + tt)*Fn + f;
                o[0] = sigm(acc[mm][nn][2] + bv0);
                o[1] = sigm(acc[mm][nn][3] + bv1);
            }
        }
    }
}

__global__ void k_init(const float* __restrict__ h0, const float* __restrict__ c0){
    int i = blockIdx.x * blockDim.x + threadIdx.x;
    g_hbuf[0][i] = h0[i];
    g_cbuf[i]    = c0[i];
}

__global__ void k_tail(float* __restrict__ out){
    int i = blockIdx.x * blockDim.x + threadIdx.x;
    out[(size_t)Bn*Tn*Fn + i]            = g_hbuf[0][i];   // hT (last write: (511+1)&1 == 0)
    out[(size_t)Bn*Tn*Fn + Bn*DUn + i]   = g_cbuf[i];      // cT
}

extern "C" void kernel_launch(void* const* d_in, const int* in_sizes, int n_in,
                              void* d_out, int out_size){
    (void)in_sizes; (void)n_in; (void)out_size;
    const float* conductor = (const float*)d_in[0];
    const float* teacher   = (const float*)d_in[1];
    const float* h0   = (const float*)d_in[2];
    const float* c0   = (const float*)d_in[3];
    const float* W    = (const float*)d_in[4];
    const float* U    = (const float*)d_in[5];
    const float* bias = (const float*)d_in[6];
    const float* Wo   = (const float*)d_in[7];
    const float* bo   = (const float*)d_in[8];
    float* out = (float*)d_out;

    k_init<<<(Bn*DUn)/256, 256>>>(h0, c0);
    k_pre<<<dim3(NG/BN, Rn/BM), 256>>>(teacher, conductor, W, bias);
    for (int t = 0; t < Tn; t++)
        k_step<<<dim3(DUn/16, Bn/BM), 256>>>(U, t);
    k_out<<<dim3(Fn/BN, Rn/BM), 256>>>(Wo, bo, out);
    k_tail<<<(Bn*DUn)/256, 256>>>(out);
}

// round 2
// speedup vs baseline: 1.0421x; 1.0421x over previous
#include <cuda_runtime.h>
#include <cstdint>
#include <math.h>

// Problem dims
#define Bn  256
#define Tn  512
#define Fn  128
#define CUn 512
#define DUn 512
#define KX  640          // Fn + CUn
#define NG  2048         // 4*DUn
#define Rn  (Bn*Tn)      // 131072

// Shared GEMM tiling for k_pre / k_out
#define BM 128
#define BN 64
#define BK 32
#define ASTR 36
#define BSTR 72

// Persistent recurrent kernel config
#define NCTA   64        // one CTA per 8 hidden units (64*8 = 512)
#define UNITS  8         // hidden units per CTA
#define CCOLS  32        // gate columns per CTA (4 gates x 8 units)
#define USTR   40        // U smem row stride (40 % 32 == 8 -> conflict-free B frags)
#define HSTR   36        // h tile row stride (36 % 32 == 4 -> conflict-free A frags)

// Scratch
__device__ float g_Zpre[(size_t)Rn * NG];    // 1 GiB: x@W + b, rows r = t*256+b
__device__ float g_H[(size_t)Rn * DUn];      // 256 MB: h history (exact fp32)
__device__ unsigned g_bar;                   // global barrier counter

__device__ __forceinline__ uint32_t f2tf(float x){
    uint32_t r; asm("cvt.rna.tf32.f32 %0, %1;" : "=r"(r) : "f"(x)); return r;
}
__device__ __forceinline__ float tf2f(uint32_t u){ return __uint_as_float(u); }
__device__ __forceinline__ void st4_tf(float* dst, float4 v){
    dst[0]=tf2f(f2tf(v.x)); dst[1]=tf2f(f2tf(v.y));
    dst[2]=tf2f(f2tf(v.z)); dst[3]=tf2f(f2tf(v.w));
}
__device__ __forceinline__ void mma_tf32(float d[4],
        uint32_t a0, uint32_t a1, uint32_t a2, uint32_t a3,
        uint32_t b0, uint32_t b1){
    asm volatile(
        "mma.sync.aligned.m16n8k8.row.col.f32.tf32.tf32.f32 "
        "{%0,%1,%2,%3}, {%4,%5,%6,%7}, {%8,%9}, {%0,%1,%2,%3};\n"
        : "+f"(d[0]), "+f"(d[1]), "+f"(d[2]), "+f"(d[3])
        : "r"(a0), "r"(a1), "r"(a2), "r"(a3), "r"(b0), "r"(b1));
}
__device__ __forceinline__ float sigm(float x){ return 1.f/(1.f + __expf(-x)); }

// ===========================================================================
// Persistent recurrent kernel
//   grid = 64 CTAs, 256 threads. CTA bx owns hidden units j0 = bx*8 .. +8,
//   i.e. U columns {q*512 + j0 + j : q in 0..3, j in 0..7}, kept in SMEM.
//   Per step: z = h_{t-1} @ U_slice (+ Zpre via cp.async), gates, c in SMEM,
//   h written exact to g_H[t]. Global barrier between steps.
// ===========================================================================
#define US_OFF  0                       // 512*40      = 20480 floats
#define AS_OFF  (512*USTR)              // 2 * 256*36  = 18432
#define ZPS_OFF (AS_OFF + 2*256*HSTR)   // 256*36      =  9216
#define CS_OFF  (ZPS_OFF + 256*HSTR)    // 256*8       =  2048
#define SM_FLOATS (CS_OFF + 256*UNITS)  // 50176 floats = 200704 B

__device__ __forceinline__ void rec_ktile(const float* As, const float* Us,
                                          float acc[4][2][4], int wm, int wn,
                                          int lane, int k0){
    const int qr = lane >> 2, qc = lane & 3;
    #pragma unroll
    for (int k8 = 0; k8 < BK; k8 += 8){
        uint32_t a[4][4];
        #pragma unroll
        for (int mt = 0; mt < 4; mt++){
            const float* ap = As + (wm*64 + mt*16 + qr) * HSTR + k8 + qc;
            a[mt][0] = __float_as_uint(ap[0]);
            a[mt][1] = __float_as_uint(ap[8*HSTR]);
            a[mt][2] = __float_as_uint(ap[4]);
            a[mt][3] = __float_as_uint(ap[8*HSTR + 4]);
        }
        uint32_t b[2][2];
        #pragma unroll
        for (int nt = 0; nt < 2; nt++){
            const float* bp = Us + (k0 + k8 + qc) * USTR + wn*16 + nt*8 + qr;
            b[nt][0] = __float_as_uint(bp[0]);
            b[nt][1] = __float_as_uint(bp[4*USTR]);
        }
        #pragma unroll
        for (int mt = 0; mt < 4; mt++)
            #pragma unroll
            for (int nt = 0; nt < 2; nt++)
                mma_tf32(acc[mt][nt], a[mt][0], a[mt][1], a[mt][2], a[mt][3],
                         b[nt][0], b[nt][1]);
    }
}

__global__ __launch_bounds__(256) void k_rec(const float* __restrict__ U,
                                             const float* __restrict__ h0,
                                             const float* __restrict__ c0,
                                             float* __restrict__ out){
    extern __shared__ float sm[];
    float* Us  = sm + US_OFF;
    float* As  = sm + AS_OFF;     // double-buffered h tiles; reused as zs
    float* zps = sm + ZPS_OFF;
    float* cs  = sm + CS_OFF;

    const int tid = threadIdx.x, lane = tid & 31, wid = tid >> 5;
    const int wm = wid >> 1, wn = wid & 1;       // 4 in M x 2 in N
    const int j0 = blockIdx.x * UNITS;

    // ---- one-time: U slice (tf32-rounded) + c0 slice into SMEM ----
    for (int i = tid; i < 512*CCOLS; i += 256){
        int k = i >> 5, n = i & 31;
        float v = U[(size_t)k*NG + (n>>3)*DUn + j0 + (n&7)];
        Us[k*USTR + n] = tf2f(f2tf(v));
    }
    for (int i = tid; i < 256*UNITS; i += 256){
        int r = i >> 3, j = i & 7;
        cs[i] = c0[(size_t)r*DUn + j0 + j];
    }
    __syncthreads();

    const uint32_t zps_base = (uint32_t)__cvta_generic_to_shared(zps);

    for (int t = 0; t < Tn; t++){
        const float* hsrc = (t == 0) ? h0 : (g_H + (size_t)(t-1)*Bn*DUn);

        // ---- async prefetch of Zpre slice for this step (lands under GEMM) ----
        #pragma unroll
        for (int i = 0; i < 8; i++){
            int s = tid + i*256;                 // 0..2047 float4 segments
            int r = s >> 3, qj = s & 7;
            int q = qj >> 1, jh = qj & 1;
            const float* src = g_Zpre + ((size_t)t*Bn + r)*NG + q*DUn + j0 + jh*4;
            uint32_t dst = zps_base + (uint32_t)(r*HSTR + q*8 + jh*4) * 4u;
            asm volatile("cp.async.ca.shared.global [%0], [%1], 16;\n"
                         :: "r"(dst), "l"(src));
        }
        asm volatile("cp.async.commit_group;\n" ::: "memory");

        // ---- pipelined GEMM: z_acc = h_prev @ U_slice ----
        float acc[4][2][4];
        #pragma unroll
        for (int mt=0;mt<4;mt++)
            #pragma unroll
            for (int nt=0;nt<2;nt++)
                #pragma unroll
                for (int i=0;i<4;i++) acc[mt][nt][i]=0.f;

        float4 v[8];
        #pragma unroll
        for (int i = 0; i < 8; i++){
            int idx = tid + i*256;
            int row = idx >> 3, c4 = (idx & 7) * 4;
            v[i] = *reinterpret_cast<const float4*>(hsrc + (size_t)row*DUn + c4);
        }
        #pragma unroll
        for (int i = 0; i < 8; i++){
            int idx = tid + i*256;
            int row = idx >> 3, c4 = (idx & 7) * 4;
            st4_tf(As + row*HSTR + c4, v[i]);
        }

        for (int kt = 0; kt < DUn/BK; kt++){
            if (kt + 1 < DUn/BK){
                int k0n = (kt + 1) * BK;
                #pragma unroll
                for (int i = 0; i < 8; i++){
                    int idx = tid + i*256;
                    int row = idx >> 3, c4 = (idx & 7) * 4;
                    v[i] = *reinterpret_cast<const float4*>(
                               hsrc + (size_t)row*DUn + k0n + c4);
                }
            }
            __syncthreads();
            rec_ktile(As + (kt & 1)*256*HSTR, Us, acc, wm, wn, lane, kt*BK);
            if (kt + 1 < DUn/BK){
                float* dst = As + ((kt + 1) & 1)*256*HSTR;
                #pragma unroll
                for (int i = 0; i < 8; i++){
                    int idx = tid + i*256;
                    int row = idx >> 3, c4 = (idx & 7) * 4;
                    st4_tf(dst + row*HSTR + c4, v[i]);
                }
            }
        }
        __syncthreads();

        // ---- stage z into smem (reuse buffer 0 of As) ----
        float* zs = As;
        const int qr = lane >> 2, qc = lane & 3;
        #pragma unroll
        for (int mt = 0; mt < 4; mt++){
            int row = wm*64 + mt*16 + qr;
            #pragma unroll
            for (int nt = 0; nt < 2; nt++){
                int col = wn*16 + nt*8 + qc*2;
                zs[row*HSTR + col]         = acc[mt][nt][0];
                zs[row*HSTR + col + 1]     = acc[mt][nt][1];
                zs[(row+8)*HSTR + col]     = acc[mt][nt][2];
                zs[(row+8)*HSTR + col + 1] = acc[mt][nt][3];
            }
        }
        asm volatile("cp.async.wait_group 0;\n" ::: "memory");
        __syncthreads();

        // ---- gate phase: 256 rows x 8 units, 8 items/thread ----
        {
            int r0 = tid >> 1;
            int j4 = (tid & 1) * 4;
            #pragma unroll
            for (int rr = 0; rr < 2; rr++){
                int r = r0 + rr*128;
                float* hdst = g_H + ((size_t)t*Bn + r)*DUn + j0;
                #pragma unroll
                for (int jj = 0; jj < 4; jj++){
                    int j = j4 + jj;
                    float zi = zs[r*HSTR + j]      + zps[r*HSTR + j];
                    float zf = zs[r*HSTR + 8  + j] + zps[r*HSTR + 8  + j];
                    float zg = zs[r*HSTR + 16 + j] + zps[r*HSTR + 16 + j];
                    float zo = zs[r*HSTR + 24 + j] + zps[r*HSTR + 24 + j];
                    float si = sigm(zi), sf = sigm(zf), so = sigm(zo);
                    float tg = tanhf(zg);
                    float c  = cs[r*UNITS + j];
                    float cn = sf*c + si*tg;
                    float hn = so * tanhf(cn);
                    cs[r*UNITS + j] = cn;
                    hdst[j] = hn;
                    if (t == Tn - 1){
                        out[(size_t)Bn*Tn*Fn + (size_t)r*DUn + j0 + j]          = hn;
                        out[(size_t)Bn*Tn*Fn + Bn*DUn + (size_t)r*DUn + j0 + j] = cn;
                    }
                }
            }
        }
        __syncthreads();

        // ---- global step barrier (monotonic counter; reset by k_init) ----
        if (t < Tn - 1){
            if (tid == 0){
                __threadfence();
                atomicAdd(&g_bar, 1u);
                unsigned target = (unsigned)NCTA * (unsigned)(t + 1);
                unsigned got;
                do {
                    asm volatile("ld.global.acquire.gpu.b32 %0, [%1];"
                                 : "=r"(got) : "l"(&g_bar));
                } while (got < target);
            }
            __syncthreads();
        }
    }
}

// ===========================================================================
// k_pre: Zpre = x @ W + bias (fully parallel, teacher forcing)
// ===========================================================================
__device__ __forceinline__ void compute_ktile(const float* As, const float* Bs,
                                              float acc[2][4][4], int wm, int wn, int lane){
    const int qr = lane >> 2, qc = lane & 3;
    #pragma unroll
    for (int k8 = 0; k8 < BK; k8 += 8){
        uint32_t a[2][4];
        #pragma unroll
        for (int mm = 0; mm < 2; mm++){
            const float* ap = As + (wm*32 + mm*16 + qr) * ASTR + k8 + qc;
            a[mm][0] = __float_as_uint(ap[0]);
            a[mm][1] = __float_as_uint(ap[8*ASTR]);
            a[mm][2] = __float_as_uint(ap[4]);
            a[mm][3] = __float_as_uint(ap[8*ASTR + 4]);
        }
        #pragma unroll
        for (int nn = 0; nn < 4; nn++){
            const float* bp = Bs + (k8 + qc) * BSTR + wn*32 + nn*8 + qr;
            uint32_t b0 = __float_as_uint(bp[0]);
            uint32_t b1 = __float_as_uint(bp[4*BSTR]);
            #pragma unroll
            for (int mm = 0; mm < 2; mm++)
                mma_tf32(acc[mm][nn], a[mm][0], a[mm][1], a[mm][2], a[mm][3], b0, b1);
        }
    }
}

__global__ __launch_bounds__(256) void k_pre(const float* __restrict__ teacher,
                                             const float* __restrict__ cond,
                                             const float* __restrict__ W,
                                             const float* __restrict__ bias){
    __shared__ float As[BM*ASTR];
    __shared__ float Bs[BK*BSTR];
    const int tid = threadIdx.x, lane = tid & 31, wid = tid >> 5;
    const int wm = wid & 3, wn = wid >> 2;
    const int n0 = blockIdx.x * BN;
    const int by = blockIdx.y;
    const int t  = by >> 1;
    const int b0 = (by & 1) * BM;

    float acc[2][4][4];
    #pragma unroll
    for (int mm=0;mm<2;mm++)
        #pragma unroll
        for (int nn=0;nn<4;nn++)
            #pragma unroll
            for (int i=0;i<4;i++) acc[mm][nn][i]=0.f;

    for (int kt = 0; kt < KX/BK; kt++){
        int k0 = kt * BK;
        #pragma unroll
        for (int i = 0; i < 4; i++){
            int idx = tid + i*256;
            int row = idx >> 3, c4 = (idx & 7) * 4;
            int b  = b0 + row;
            int kg = k0 + c4;
            float4 v;
            if (kg < Fn){
                if (t == 0) v = make_float4(0.f,0.f,0.f,0.f);
                else v = *reinterpret_cast<const float4*>(
                            teacher + ((size_t)b*Tn + (t-1))*Fn + kg);
            } else {
                v = *reinterpret_cast<const float4*>(
                            cond + ((size_t)b*Tn + t)*CUn + (kg - Fn));
            }
            st4_tf(As + row*ASTR + c4, v);
        }
        #pragma unroll
        for (int i = 0; i < 2; i++){
            int idx = tid + i*256;
            int kr = idx >> 4, c4 = (idx & 15) * 4;
            float4 v = *reinterpret_cast<const float4*>(W + (size_t)(k0+kr)*NG + n0 + c4);
            st4_tf(Bs + kr*BSTR + c4, v);
        }
        __syncthreads();
        compute_ktile(As, Bs, acc, wm, wn, lane);
        __syncthreads();
    }

    const int qr = lane >> 2, qc = lane & 3;
    const size_t r0 = (size_t)by * BM;
    #pragma unroll
    for (int mm=0;mm<2;mm++){
        int row = wm*32 + mm*16 + qr;
        #pragma unroll
        for (int nn=0;nn<4;nn++){
            int col = n0 + wn*32 + nn*8 + qc*2;
            float bv0 = bias[col], bv1 = bias[col+1];
            float* z0 = g_Zpre + (r0 + row) * NG + col;
            z0[0] = acc[mm][nn][0] + bv0;
            z0[1] = acc[mm][nn][1] + bv1;
            float* z1 = g_Zpre + (r0 + row + 8) * NG + col;
            z1[0] = acc[mm][nn][2] + bv0;
            z1[1] = acc[mm][nn][3] + bv1;
        }
    }
}

// ===========================================================================
// k_out: out[b,t,f] = sigmoid(H @ Wo + bo)
// ===========================================================================
__global__ __launch_bounds__(256) void k_out(const float* __restrict__ Wo,
                                             const float* __restrict__ bo,
                                             float* __restrict__ out){
    __shared__ float As[BM*ASTR];
    __shared__ float Bs[BK*BSTR];
    const int tid = threadIdx.x, lane = tid & 31, wid = tid >> 5;
    const int wm = wid & 3, wn = wid >> 2;
    const int f0 = blockIdx.x * BN;
    const int r0 = blockIdx.y * BM;

    float acc[2][4][4];
    #pragma unroll
    for (int mm=0;mm<2;mm++)
        #pragma unroll
        for (int nn=0;nn<4;nn++)
            #pragma unroll
            for (int i=0;i<4;i++) acc[mm][nn][i]=0.f;

    for (int kt = 0; kt < DUn/BK; kt++){
        int k0 = kt * BK;
        #pragma unroll
        for (int i = 0; i < 4; i++){
            int idx = tid + i*256;
            int row = idx >> 3, c4 = (idx & 7) * 4;
            float4 v = *reinterpret_cast<const float4*>(
                            g_H + (size_t)(r0+row)*DUn + k0 + c4);
            st4_tf(As + row*ASTR + c4, v);
        }
        #pragma unroll
        for (int i = 0; i < 2; i++){
            int idx = tid + i*256;
            int kr = idx >> 4, c4 = (idx & 15) * 4;
            float4 v = *reinterpret_cast<const float4*>(
                            Wo + (size_t)(k0+kr)*Fn + f0 + c4);
            st4_tf(Bs + kr*BSTR + c4, v);
        }
        __syncthreads();
        compute_ktile(As, Bs, acc, wm, wn, lane);
        __syncthreads();
    }

    const int qr = lane >> 2, qc = lane & 3;
    #pragma unroll
    for (int mm=0;mm<2;mm++){
        int r = r0 + wm*32 + mm*16 + qr;
        #pragma unroll
        for (int nn=0;nn<4;nn++){
            int f = f0 + wn*32 + nn*8 + qc*2;
            float bv0 = bo[f], bv1 = bo[f+1];
            {
                int b = r & (Bn-1), tt = r >> 8;
                float* o = out + ((size_t)b*Tn + tt)*Fn + f;
                o[0] = sigm(acc[mm][nn][0] + bv0);
                o[1] = sigm(acc[mm][nn][1] + bv1);
            }
            {
                int r2 = r + 8;
                int b = r2 & (Bn-1), tt = r2 >> 8;
                float* o = out + ((size_t)b*Tn + tt)*Fn + f;
                o[0] = sigm(acc[mm][nn][2] + bv0);
                o[1] = sigm(acc[mm][nn][3] + bv1);
            }
        }
    }
}

__global__ void k_init(){
    g_bar = 0u;
}

extern "C" void kernel_launch(void* const* d_in, const int* in_sizes, int n_in,
                              void* d_out, int out_size){
    (void)in_sizes; (void)n_in; (void)out_size;
    const float* conductor = (const float*)d_in[0];
    const float* teacher   = (const float*)d_in[1];
    const float* h0   = (const float*)d_in[2];
    const float* c0   = (const float*)d_in[3];
    const float* W    = (const float*)d_in[4];
    const float* U    = (const float*)d_in[5];
    const float* bias = (const float*)d_in[6];
    const float* Wo   = (const float*)d_in[7];
    const float* bo   = (const float*)d_in[8];
    float* out = (float*)d_out;

    cudaFuncSetAttribute(k_rec, cudaFuncAttributeMaxDynamicSharedMemorySize,
                         SM_FLOATS * (int)sizeof(float));

    k_init<<<1, 1>>>();
    k_pre<<<dim3(NG/BN, Rn/BM), 256>>>(teacher, conductor, W, bias);
    k_rec<<<NCTA, 256, SM_FLOATS * sizeof(float)>>>(U, h0, c0, out);
    k_out<<<dim3(Fn/BN, Rn/BM), 256>>>(Wo, bo, out);
}

// round 3
// speedup vs baseline: 1.1822x; 1.1344x over previous
#include <cuda_runtime.h>
#include <cstdint>
#include <math.h>

// Problem dims
#define Bn  256
#define Tn  512
#define Fn  128
#define CUn 512
#define DUn 512
#define KX  640          // Fn + CUn
#define NG  2048         // 4*DUn
#define Rn  (Bn*Tn)      // 131072

// k_pre / k_out tiling
#define BM 128
#define BN 64
#define BK 32
#define ASTR 36
#define BSTR 72

// Persistent recurrent kernel config
#define NCTA   64        // CTA bx owns hidden units j0 = bx*8..+8 (4 gates x 8 = 32 cols)
#define UNITS  8
#define CCOLS  32
#define USTR   40        // 40 % 32 == 8 -> conflict-free B frag loads
#define HSTR   36        // 36 % 32 == 4 -> conflict-free A frag loads
#define ZSTR   36

// Scratch
__device__ float g_Zpre[(size_t)Rn * NG];    // 1 GiB
__device__ float g_H[(size_t)Rn * DUn];      // 256 MB, tf32-rounded h history
__device__ float g_h0r[Bn * DUn];            // tf32-rounded h0
__device__ unsigned g_bar;

__device__ __forceinline__ uint32_t f2tf(float x){
    uint32_t r; asm("cvt.rna.tf32.f32 %0, %1;" : "=r"(r) : "f"(x)); return r;
}
__device__ __forceinline__ float tf2f(uint32_t u){ return __uint_as_float(u); }
__device__ __forceinline__ void st4_tf(float* dst, float4 v){
    dst[0]=tf2f(f2tf(v.x)); dst[1]=tf2f(f2tf(v.y));
    dst[2]=tf2f(f2tf(v.z)); dst[3]=tf2f(f2tf(v.w));
}
__device__ __forceinline__ void mma_tf32(float d[4],
        uint32_t a0, uint32_t a1, uint32_t a2, uint32_t a3,
        uint32_t b0, uint32_t b1){
    asm volatile(
        "mma.sync.aligned.m16n8k8.row.col.f32.tf32.tf32.f32 "
        "{%0,%1,%2,%3}, {%4,%5,%6,%7}, {%8,%9}, {%0,%1,%2,%3};\n"
        : "+f"(d[0]), "+f"(d[1]), "+f"(d[2]), "+f"(d[3])
        : "r"(a0), "r"(a1), "r"(a2), "r"(a3), "r"(b0), "r"(b1));
}
__device__ __forceinline__ float sigm(float x){ return 1.f/(1.f + __expf(-x)); }

#define CPA16(dst_u32, src_ptr) \
    asm volatile("cp.async.ca.shared.global [%0], [%1], 16;\n" \
                 :: "r"(dst_u32), "l"(src_ptr))
#define CPA_COMMIT() asm volatile("cp.async.commit_group;\n" ::: "memory")

// ===========================================================================
// Persistent recurrent kernel: 64 CTAs x 512 threads.
// SMEM: Us[512*40] | As: 3 stages of [256*36] | zps[256*36]
// ===========================================================================
#define US_OFF   0
#define AS_OFF   (512*USTR)                  // 20480
#define ZPS_OFF  (AS_OFF + 3*256*HSTR)       // 20480 + 27648 = 48128
#define SM_FLOATS (ZPS_OFF + 256*ZSTR)       // 57344 floats = 229376 B

__device__ __forceinline__ void rec_ktile(const float* As, const float* Us,
                                          float acc[2][2][4], int wm, int wn,
                                          int lane, int k0){
    const int qr = lane >> 2, qc = lane & 3;
    #pragma unroll
    for (int k8 = 0; k8 < BK; k8 += 8){
        uint32_t a[2][4];
        #pragma unroll
        for (int mt = 0; mt < 2; mt++){
            const float* ap = As + (wm*32 + mt*16 + qr) * HSTR + k8 + qc;
            a[mt][0] = __float_as_uint(ap[0]);
            a[mt][1] = __float_as_uint(ap[8*HSTR]);
            a[mt][2] = __float_as_uint(ap[4]);
            a[mt][3] = __float_as_uint(ap[8*HSTR + 4]);
        }
        uint32_t b[2][2];
        #pragma unroll
        for (int nt = 0; nt < 2; nt++){
            const float* bp = Us + (k0 + k8 + qc) * USTR + wn*16 + nt*8 + qr;
            b[nt][0] = __float_as_uint(bp[0]);
            b[nt][1] = __float_as_uint(bp[4*USTR]);
        }
        #pragma unroll
        for (int mt = 0; mt < 2; mt++)
            #pragma unroll
            for (int nt = 0; nt < 2; nt++)
                mma_tf32(acc[mt][nt], a[mt][0], a[mt][1], a[mt][2], a[mt][3],
                         b[nt][0], b[nt][1]);
    }
}

__global__ __launch_bounds__(512) void k_rec(const float* __restrict__ U,
                                             const float* __restrict__ c0,
                                             float* __restrict__ out){
    extern __shared__ float sm[];
    float* Us  = sm + US_OFF;
    float* As  = sm + AS_OFF;
    float* zps = sm + ZPS_OFF;

    const int tid = threadIdx.x, lane = tid & 31, wid = tid >> 5;
    const int wm = wid >> 1, wn = wid & 1;       // 8 in M x 2 in N
    const int j0 = blockIdx.x * UNITS;

    // ---- one-time: U slice (tf32) into SMEM, c slice into registers ----
    for (int i = tid; i < 512*CCOLS; i += 512){
        int k = i >> 5, n = i & 31;
        float v = U[(size_t)k*NG + (n>>3)*DUn + j0 + (n&7)];
        Us[k*USTR + n] = tf2f(f2tf(v));
    }
    const int gr = tid >> 1;                     // gate-phase row 0..255
    const int gj4 = (tid & 1) * 4;               // unit offset 0 or 4
    float4 cv = *reinterpret_cast<const float4*>(c0 + (size_t)gr*DUn + j0 + gj4);
    float creg[4] = {cv.x, cv.y, cv.z, cv.w};
    __syncthreads();

    const uint32_t as_u32  = (uint32_t)__cvta_generic_to_shared(As);
    const uint32_t zps_u32 = (uint32_t)__cvta_generic_to_shared(zps);

    for (int t = 0; t < Tn; t++){
        const float* hsrc = (t == 0) ? g_h0r : (g_H + (size_t)(t-1)*Bn*DUn);

        // ---- group 0: zps slice for this step ----
        #pragma unroll
        for (int i = 0; i < 4; i++){
            int s = tid + i*512;                 // 0..2047
            int r = s >> 3, qj = s & 7;
            int q = qj >> 1, jh = (qj & 1) * 4;
            const float* src = g_Zpre + ((size_t)t*Bn + r)*NG + q*DUn + j0 + jh;
            CPA16(zps_u32 + (uint32_t)(r*ZSTR + q*8 + jh)*4u, src);
        }
        CPA_COMMIT();

        // ---- prologue: tiles 0,1 into stages 0,1 ----
        #pragma unroll
        for (int pt = 0; pt < 2; pt++){
            uint32_t st = as_u32 + (uint32_t)(pt*256*HSTR)*4u;
            #pragma unroll
            for (int i = 0; i < 4; i++){
                int s = tid + i*512;
                int r = s >> 3, ch = (s & 7) * 4;
                CPA16(st + (uint32_t)(r*HSTR + ch)*4u,
                      hsrc + (size_t)r*DUn + pt*BK + ch);
            }
            CPA_COMMIT();
        }

        float acc[2][2][4];
        #pragma unroll
        for (int mt=0;mt<2;mt++)
            #pragma unroll
            for (int nt=0;nt<2;nt++)
                #pragma unroll
                for (int i=0;i<4;i++) acc[mt][nt][i]=0.f;

        for (int kt = 0; kt < DUn/BK; kt++){
            if (kt < DUn/BK - 1)
                asm volatile("cp.async.wait_group 1;\n" ::: "memory");
            else
                asm volatile("cp.async.wait_group 0;\n" ::: "memory");
            __syncthreads();
            if (kt + 2 < DUn/BK){
                int s3 = (kt + 2) % 3;
                uint32_t st = as_u32 + (uint32_t)(s3*256*HSTR)*4u;
                int k0n = (kt + 2) * BK;
                #pragma unroll
                for (int i = 0; i < 4; i++){
                    int s = tid + i*512;
                    int r = s >> 3, ch = (s & 7) * 4;
                    CPA16(st + (uint32_t)(r*HSTR + ch)*4u,
                          hsrc + (size_t)r*DUn + k0n + ch);
                }
                CPA_COMMIT();
            }
            rec_ktile(As + (kt % 3)*256*HSTR, Us, acc, wm, wn, lane, kt*BK);
        }
        __syncthreads();

        // ---- stage z into stage-0 buffer ----
        float* zs = As;
        const int qr = lane >> 2, qc = lane & 3;
        #pragma unroll
        for (int mt = 0; mt < 2; mt++){
            int row = wm*32 + mt*16 + qr;
            #pragma unroll
            for (int nt = 0; nt < 2; nt++){
                int col = wn*16 + nt*8 + qc*2;
                zs[row*HSTR + col]         = acc[mt][nt][0];
                zs[row*HSTR + col + 1]     = acc[mt][nt][1];
                zs[(row+8)*HSTR + col]     = acc[mt][nt][2];
                zs[(row+8)*HSTR + col + 1] = acc[mt][nt][3];
            }
        }
        __syncthreads();

        // ---- gate phase: each thread 1 row x 4 units ----
        {
            float hv[4];
            #pragma unroll
            for (int jj = 0; jj < 4; jj++){
                int j = gj4 + jj;
                float zi = zs[gr*HSTR + j]      + zps[gr*ZSTR + j];
                float zf = zs[gr*HSTR + 8  + j] + zps[gr*ZSTR + 8  + j];
                float zg = zs[gr*HSTR + 16 + j] + zps[gr*ZSTR + 16 + j];
                float zo = zs[gr*HSTR + 24 + j] + zps[gr*ZSTR + 24 + j];
                float si = sigm(zi), sf = sigm(zf), so = sigm(zo);
                float tg = tanhf(zg);
                float cn = sf*creg[jj] + si*tg;
                float hn = so * tanhf(cn);
                creg[jj] = cn;
                hv[jj] = tf2f(f2tf(hn));         // h only ever feeds tf32 GEMMs
            }
            *reinterpret_cast<float4*>(g_H + ((size_t)t*Bn + gr)*DUn + j0 + gj4)
                = make_float4(hv[0], hv[1], hv[2], hv[3]);
            if (t == Tn - 1){
                *reinterpret_cast<float4*>(out + (size_t)Bn*Tn*Fn
                                           + (size_t)gr*DUn + j0 + gj4)
                    = make_float4(hv[0], hv[1], hv[2], hv[3]);
                *reinterpret_cast<float4*>(out + (size_t)Bn*Tn*Fn + Bn*DUn
                                           + (size_t)gr*DUn + j0 + gj4)
                    = make_float4(creg[0], creg[1], creg[2], creg[3]);
            }
        }
        __syncthreads();

        // ---- global step barrier ----
        if (t < Tn - 1){
            if (tid == 0){
                __threadfence();
                atomicAdd(&g_bar, 1u);
                unsigned target = (unsigned)NCTA * (unsigned)(t + 1);
                unsigned got;
                do {
                    asm volatile("ld.global.acquire.gpu.b32 %0, [%1];"
                                 : "=r"(got) : "l"(&g_bar));
                } while (got < target);
            }
            __syncthreads();
        }
    }
}

// ===========================================================================
// k_pre: Zpre = x @ W + bias
// ===========================================================================
__device__ __forceinline__ void compute_ktile(const float* As, const float* Bs,
                                              float acc[2][4][4], int wm, int wn, int lane){
    const int qr = lane >> 2, qc = lane & 3;
    #pragma unroll
    for (int k8 = 0; k8 < BK; k8 += 8){
        uint32_t a[2][4];
        #pragma unroll
        for (int mm = 0; mm < 2; mm++){
            const float* ap = As + (wm*32 + mm*16 + qr) * ASTR + k8 + qc;
            a[mm][0] = __float_as_uint(ap[0]);
            a[mm][1] = __float_as_uint(ap[8*ASTR]);
            a[mm][2] = __float_as_uint(ap[4]);
            a[mm][3] = __float_as_uint(ap[8*ASTR + 4]);
        }
        #pragma unroll
        for (int nn = 0; nn < 4; nn++){
            const float* bp = Bs + (k8 + qc) * BSTR + wn*32 + nn*8 + qr;
            uint32_t b0 = __float_as_uint(bp[0]);
            uint32_t b1 = __float_as_uint(bp[4*BSTR]);
            #pragma unroll
            for (int mm = 0; mm < 2; mm++)
                mma_tf32(acc[mm][nn], a[mm][0], a[mm][1], a[mm][2], a[mm][3], b0, b1);
        }
    }
}

__global__ __launch_bounds__(256) void k_pre(const float* __restrict__ teacher,
                                             const float* __restrict__ cond,
                                             const float* __restrict__ W,
                                             const float* __restrict__ bias){
    __shared__ float As[BM*ASTR];
    __shared__ float Bs[BK*BSTR];
    const int tid = threadIdx.x, lane = tid & 31, wid = tid >> 5;
    const int wm = wid & 3, wn = wid >> 2;
    const int n0 = blockIdx.x * BN;
    const int by = blockIdx.y;
    const int t  = by >> 1;
    const int b0 = (by & 1) * BM;

    float acc[2][4][4];
    #pragma unroll
    for (int mm=0;mm<2;mm++)
        #pragma unroll
        for (int nn=0;nn<4;nn++)
            #pragma unroll
            for (int i=0;i<4;i++) acc[mm][nn][i]=0.f;

    for (int kt = 0; kt < KX/BK; kt++){
        int k0 = kt * BK;
        #pragma unroll
        for (int i = 0; i < 4; i++){
            int idx = tid + i*256;
            int row = idx >> 3, c4 = (idx & 7) * 4;
            int b  = b0 + row;
            int kg = k0 + c4;
            float4 v;
            if (kg < Fn){
                if (t == 0) v = make_float4(0.f,0.f,0.f,0.f);
                else v = *reinterpret_cast<const float4*>(
                            teacher + ((size_t)b*Tn + (t-1))*Fn + kg);
            } else {
                v = *reinterpret_cast<const float4*>(
                            cond + ((size_t)b*Tn + t)*CUn + (kg - Fn));
            }
            st4_tf(As + row*ASTR + c4, v);
        }
        #pragma unroll
        for (int i = 0; i < 2; i++){
            int idx = tid + i*256;
            int kr = idx >> 4, c4 = (idx & 15) * 4;
            float4 v = *reinterpret_cast<const float4*>(W + (size_t)(k0+kr)*NG + n0 + c4);
            st4_tf(Bs + kr*BSTR + c4, v);
        }
        __syncthreads();
        compute_ktile(As, Bs, acc, wm, wn, lane);
        __syncthreads();
    }

    const int qr = lane >> 2, qc = lane & 3;
    const size_t r0 = (size_t)by * BM;
    #pragma unroll
    for (int mm=0;mm<2;mm++){
        int row = wm*32 + mm*16 + qr;
        #pragma unroll
        for (int nn=0;nn<4;nn++){
            int col = n0 + wn*32 + nn*8 + qc*2;
            float bv0 = bias[col], bv1 = bias[col+1];
            float* z0 = g_Zpre + (r0 + row) * NG + col;
            z0[0] = acc[mm][nn][0] + bv0;
            z0[1] = acc[mm][nn][1] + bv1;
            float* z1 = g_Zpre + (r0 + row + 8) * NG + col;
            z1[0] = acc[mm][nn][2] + bv0;
            z1[1] = acc[mm][nn][3] + bv1;
        }
    }
}

// ===========================================================================
// k_out: out[b,t,f] = sigmoid(H @ Wo + bo)
// ===========================================================================
__global__ __launch_bounds__(256) void k_out(const float* __restrict__ Wo,
                                             const float* __restrict__ bo,
                                             float* __restrict__ out){
    __shared__ float As[BM*ASTR];
    __shared__ float Bs[BK*BSTR];
    const int tid = threadIdx.x, lane = tid & 31, wid = tid >> 5;
    const int wm = wid & 3, wn = wid >> 2;
    const int f0 = blockIdx.x * BN;
    const int r0 = blockIdx.y * BM;

    float acc[2][4][4];
    #pragma unroll
    for (int mm=0;mm<2;mm++)
        #pragma unroll
        for (int nn=0;nn<4;nn++)
            #pragma unroll
            for (int i=0;i<4;i++) acc[mm][nn][i]=0.f;

    for (int kt = 0; kt < DUn/BK; kt++){
        int k0 = kt * BK;
        #pragma unroll
        for (int i = 0; i < 4; i++){
            int idx = tid + i*256;
            int row = idx >> 3, c4 = (idx & 7) * 4;
            float4 v = *reinterpret_cast<const float4*>(
                            g_H + (size_t)(r0+row)*DUn + k0 + c4);
            st4_tf(As + row*ASTR + c4, v);
        }
        #pragma unroll
        for (int i = 0; i < 2; i++){
            int idx = tid + i*256;
            int kr = idx >> 4, c4 = (idx & 15) * 4;
            float4 v = *reinterpret_cast<const float4*>(
                            Wo + (size_t)(k0+kr)*Fn + f0 + c4);
            st4_tf(Bs + kr*BSTR + c4, v);
        }
        __syncthreads();
        compute_ktile(As, Bs, acc, wm, wn, lane);
        __syncthreads();
    }

    const int qr = lane >> 2, qc = lane & 3;
    #pragma unroll
    for (int mm=0;mm<2;mm++){
        int r = r0 + wm*32 + mm*16 + qr;
        #pragma unroll
        for (int nn=0;nn<4;nn++){
            int f = f0 + wn*32 + nn*8 + qc*2;
            float bv0 = bo[f], bv1 = bo[f+1];
            {
                int b = r & (Bn-1), tt = r >> 8;
                float* o = out + ((size_t)b*Tn + tt)*Fn + f;
                o[0] = sigm(acc[mm][nn][0] + bv0);
                o[1] = sigm(acc[mm][nn][1] + bv1);
            }
            {
                int r2 = r + 8;
                int b = r2 & (Bn-1), tt = r2 >> 8;
                float* o = out + ((size_t)b*Tn + tt)*Fn + f;
                o[0] = sigm(acc[mm][nn][2] + bv0);
                o[1] = sigm(acc[mm][nn][3] + bv1);
            }
        }
    }
}

__global__ void k_init(const float* __restrict__ h0){
    int i = blockIdx.x * blockDim.x + threadIdx.x;
    if (i == 0) g_bar = 0u;
    g_h0r[i] = tf2f(f2tf(h0[i]));
}

extern "C" void kernel_launch(void* const* d_in, const int* in_sizes, int n_in,
                              void* d_out, int out_size){
    (void)in_sizes; (void)n_in; (void)out_size;
    const float* conductor = (const float*)d_in[0];
    const float* teacher   = (const float*)d_in[1];
    const float* h0   = (const float*)d_in[2];
    const float* c0   = (const float*)d_in[3];
    const float* W    = (const float*)d_in[4];
    const float* U    = (const float*)d_in[5];
    const float* bias = (const float*)d_in[6];
    const float* Wo   = (const float*)d_in[7];
    const float* bo   = (const float*)d_in[8];
    float* out = (float*)d_out;

    cudaFuncSetAttribute(k_rec, cudaFuncAttributeMaxDynamicSharedMemorySize,
                         SM_FLOATS * (int)sizeof(float));

    k_init<<<(Bn*DUn)/256, 256>>>(h0);
    k_pre<<<dim3(NG/BN, Rn/BM), 256>>>(teacher, conductor, W, bias);
    k_rec<<<NCTA, 512, SM_FLOATS * sizeof(float)>>>(U, c0, out);
    k_out<<<dim3(Fn/BN, Rn/BM), 256>>>(Wo, bo, out);
}

// round 4
// speedup vs baseline: 1.4756x; 1.2482x over previous
#include <cuda_runtime.h>
#include <cstdint>
#include <math.h>

// Problem dims
#define Bn  256
#define Tn  512
#define Fn  128
#define CUn 512
#define DUn 512
#define KX  640          // Fn + CUn
#define NG  2048         // 4*DUn
#define Rn  (Bn*Tn)      // 131072

// producer / k_out tiling
#define BM 128
#define BN 64
#define BK 32
#define ASTR 36
#define BSTR 72

// Consumer (recurrent) config
#define NREC   64        // consumer CTAs; CTA bx owns hidden units j0 = bx*8..+8
#define NCTA_ALL 148
#define NPRE   (NCTA_ALL - NREC)
#define UNITS  8
#define CCOLS  32
#define USTR   40
#define HSTR   36
#define ZSTR   36
#define TILES_PER_T 64                    // (256/128) * (2048/64)
#define TOTAL_TILES (Tn * TILES_PER_T)

// Scratch
__device__ float g_Zpre[(size_t)Rn * NG];    // 1 GiB
__device__ float g_H[(size_t)Rn * DUn];      // 256 MB, tf32-rounded h history
__device__ float g_h0r[Bn * DUn];
__device__ unsigned g_bar;
__device__ unsigned g_work;
__device__ unsigned g_zdone[Tn];

__device__ __forceinline__ uint32_t f2tf(float x){
    uint32_t r; asm("cvt.rna.tf32.f32 %0, %1;" : "=r"(r) : "f"(x)); return r;
}
__device__ __forceinline__ float tf2f(uint32_t u){ return __uint_as_float(u); }
__device__ __forceinline__ void st4_tf(float* dst, float4 v){
    dst[0]=tf2f(f2tf(v.x)); dst[1]=tf2f(f2tf(v.y));
    dst[2]=tf2f(f2tf(v.z)); dst[3]=tf2f(f2tf(v.w));
}
__device__ __forceinline__ void mma_tf32(float d[4],
        uint32_t a0, uint32_t a1, uint32_t a2, uint32_t a3,
        uint32_t b0, uint32_t b1){
    asm volatile(
        "mma.sync.aligned.m16n8k8.row.col.f32.tf32.tf32.f32 "
        "{%0,%1,%2,%3}, {%4,%5,%6,%7}, {%8,%9}, {%0,%1,%2,%3};\n"
        : "+f"(d[0]), "+f"(d[1]), "+f"(d[2]), "+f"(d[3])
        : "r"(a0), "r"(a1), "r"(a2), "r"(a3), "r"(b0), "r"(b1));
}
__device__ __forceinline__ float sigm(float x){ return 1.f/(1.f + __expf(-x)); }

#define CPA16(dst_u32, src_ptr) \
    asm volatile("cp.async.ca.shared.global [%0], [%1], 16;\n" \
                 :: "r"(dst_u32), "l"(src_ptr))
#define CPA_COMMIT() asm volatile("cp.async.commit_group;\n" ::: "memory")

// SMEM layout (consumer; producer uses a prefix)
#define US_OFF   0
#define AS_OFF   (512*USTR)                  // 20480
#define ZPS_OFF  (AS_OFF + 3*256*HSTR)       // 48128
#define SM_FLOATS (ZPS_OFF + 256*ZSTR)       // 57344 floats = 229376 B

// ===========================================================================
// Consumer: recurrent LSTM steps (identical math to round 3)
// ===========================================================================
__device__ __forceinline__ void rec_ktile(const float* As, const float* Us,
                                          float acc[2][2][4], int wm, int wn,
                                          int lane, int k0){
    const int qr = lane >> 2, qc = lane & 3;
    #pragma unroll
    for (int k8 = 0; k8 < BK; k8 += 8){
        uint32_t a[2][4];
        #pragma unroll
        for (int mt = 0; mt < 2; mt++){
            const float* ap = As + (wm*32 + mt*16 + qr) * HSTR + k8 + qc;
            a[mt][0] = __float_as_uint(ap[0]);
            a[mt][1] = __float_as_uint(ap[8*HSTR]);
            a[mt][2] = __float_as_uint(ap[4]);
            a[mt][3] = __float_as_uint(ap[8*HSTR + 4]);
        }
        uint32_t b[2][2];
        #pragma unroll
        for (int nt = 0; nt < 2; nt++){
            const float* bp = Us + (k0 + k8 + qc) * USTR + wn*16 + nt*8 + qr;
            b[nt][0] = __float_as_uint(bp[0]);
            b[nt][1] = __float_as_uint(bp[4*USTR]);
        }
        #pragma unroll
        for (int mt = 0; mt < 2; mt++)
            #pragma unroll
            for (int nt = 0; nt < 2; nt++)
                mma_tf32(acc[mt][nt], a[mt][0], a[mt][1], a[mt][2], a[mt][3],
                         b[nt][0], b[nt][1]);
    }
}

__device__ void consumer_role(const float* __restrict__ U,
                              const float* __restrict__ c0,
                              float* __restrict__ out,
                              float* sm){
    float* Us  = sm + US_OFF;
    float* As  = sm + AS_OFF;
    float* zps = sm + ZPS_OFF;

    const int tid = threadIdx.x, lane = tid & 31, wid = tid >> 5;
    const int wm = wid >> 1, wn = wid & 1;       // 8 in M x 2 in N
    const int j0 = blockIdx.x * UNITS;

    for (int i = tid; i < 512*CCOLS; i += 512){
        int k = i >> 5, n = i & 31;
        float v = U[(size_t)k*NG + (n>>3)*DUn + j0 + (n&7)];
        Us[k*USTR + n] = tf2f(f2tf(v));
    }
    const int gr = tid >> 1;
    const int gj4 = (tid & 1) * 4;
    float4 cv = *reinterpret_cast<const float4*>(c0 + (size_t)gr*DUn + j0 + gj4);
    float creg[4] = {cv.x, cv.y, cv.z, cv.w};
    __syncthreads();

    const uint32_t as_u32  = (uint32_t)__cvta_generic_to_shared(As);
    const uint32_t zps_u32 = (uint32_t)__cvta_generic_to_shared(zps);

    for (int t = 0; t < Tn; t++){
        const float* hsrc = (t == 0) ? g_h0r : (g_H + (size_t)(t-1)*Bn*DUn);

        // wait for producers: all 64 Zpre tiles of step t done
        if (tid == 0){
            unsigned got;
            do {
                asm volatile("ld.global.acquire.gpu.b32 %0, [%1];"
                             : "=r"(got) : "l"(&g_zdone[t]));
            } while (got < (unsigned)TILES_PER_T);
        }
        __syncthreads();

        // group 0: zps slice
        #pragma unroll
        for (int i = 0; i < 4; i++){
            int s = tid + i*512;
            int r = s >> 3, qj = s & 7;
            int q = qj >> 1, jh = (qj & 1) * 4;
            const float* src = g_Zpre + ((size_t)t*Bn + r)*NG + q*DUn + j0 + jh;
            CPA16(zps_u32 + (uint32_t)(r*ZSTR + q*8 + jh)*4u, src);
        }
        CPA_COMMIT();

        // prologue: h tiles 0,1
        #pragma unroll
        for (int pt = 0; pt < 2; pt++){
            uint32_t st = as_u32 + (uint32_t)(pt*256*HSTR)*4u;
            #pragma unroll
            for (int i = 0; i < 4; i++){
                int s = tid + i*512;
                int r = s >> 3, ch = (s & 7) * 4;
                CPA16(st + (uint32_t)(r*HSTR + ch)*4u,
                      hsrc + (size_t)r*DUn + pt*BK + ch);
            }
            CPA_COMMIT();
        }

        float acc[2][2][4];
        #pragma unroll
        for (int mt=0;mt<2;mt++)
            #pragma unroll
            for (int nt=0;nt<2;nt++)
                #pragma unroll
                for (int i=0;i<4;i++) acc[mt][nt][i]=0.f;

        for (int kt = 0; kt < DUn/BK; kt++){
            if (kt < DUn/BK - 1)
                asm volatile("cp.async.wait_group 1;\n" ::: "memory");
            else
                asm volatile("cp.async.wait_group 0;\n" ::: "memory");
            __syncthreads();
            if (kt + 2 < DUn/BK){
                int s3 = (kt + 2) % 3;
                uint32_t st = as_u32 + (uint32_t)(s3*256*HSTR)*4u;
                int k0n = (kt + 2) * BK;
                #pragma unroll
                for (int i = 0; i < 4; i++){
                    int s = tid + i*512;
                    int r = s >> 3, ch = (s & 7) * 4;
                    CPA16(st + (uint32_t)(r*HSTR + ch)*4u,
                          hsrc + (size_t)r*DUn + k0n + ch);
                }
                CPA_COMMIT();
            }
            rec_ktile(As + (kt % 3)*256*HSTR, Us, acc, wm, wn, lane, kt*BK);
        }
        __syncthreads();

        // stage z
        float* zs = As;
        const int qr = lane >> 2, qc = lane & 3;
        #pragma unroll
        for (int mt = 0; mt < 2; mt++){
            int row = wm*32 + mt*16 + qr;
            #pragma unroll
            for (int nt = 0; nt < 2; nt++){
                int col = wn*16 + nt*8 + qc*2;
                zs[row*HSTR + col]         = acc[mt][nt][0];
                zs[row*HSTR + col + 1]     = acc[mt][nt][1];
                zs[(row+8)*HSTR + col]     = acc[mt][nt][2];
                zs[(row+8)*HSTR + col + 1] = acc[mt][nt][3];
            }
        }
        __syncthreads();

        // gates
        {
            float hv[4];
            #pragma unroll
            for (int jj = 0; jj < 4; jj++){
                int j = gj4 + jj;
                float zi = zs[gr*HSTR + j]      + zps[gr*ZSTR + j];
                float zf = zs[gr*HSTR + 8  + j] + zps[gr*ZSTR + 8  + j];
                float zg = zs[gr*HSTR + 16 + j] + zps[gr*ZSTR + 16 + j];
                float zo = zs[gr*HSTR + 24 + j] + zps[gr*ZSTR + 24 + j];
                float si = sigm(zi), sf = sigm(zf), so = sigm(zo);
                float tg = tanhf(zg);
                float cn = sf*creg[jj] + si*tg;
                float hn = so * tanhf(cn);
                creg[jj] = cn;
                hv[jj] = tf2f(f2tf(hn));
            }
            *reinterpret_cast<float4*>(g_H + ((size_t)t*Bn + gr)*DUn + j0 + gj4)
                = make_float4(hv[0], hv[1], hv[2], hv[3]);
            if (t == Tn - 1){
                *reinterpret_cast<float4*>(out + (size_t)Bn*Tn*Fn
                                           + (size_t)gr*DUn + j0 + gj4)
                    = make_float4(hv[0], hv[1], hv[2], hv[3]);
                *reinterpret_cast<float4*>(out + (size_t)Bn*Tn*Fn + Bn*DUn
                                           + (size_t)gr*DUn + j0 + gj4)
                    = make_float4(creg[0], creg[1], creg[2], creg[3]);
            }
        }
        __threadfence();          // make every thread's h stores gpu-visible
        __syncthreads();

        // global step barrier among the 64 consumer CTAs
        if (t < Tn - 1){
            if (tid == 0){
                atomicAdd(&g_bar, 1u);
                unsigned target = (unsigned)NREC * (unsigned)(t + 1);
                unsigned got;
                do {
                    asm volatile("ld.global.acquire.gpu.b32 %0, [%1];"
                                 : "=r"(got) : "l"(&g_bar));
                } while (got < target);
            }
            __syncthreads();
        }
    }
}

// ===========================================================================
// Producer: Zpre tiles (t-major work queue), 512 threads, 4x4 warps, 32x16 warptile
// ===========================================================================
__device__ void producer_role(const float* __restrict__ teacher,
                              const float* __restrict__ cond,
                              const float* __restrict__ W,
                              const float* __restrict__ bias,
                              float* sm){
    float* As = sm;                       // 128*36
    float* Bs = sm + BM*ASTR;             // 32*72
    __shared__ unsigned s_tile;
    const int tid = threadIdx.x, lane = tid & 31, wid = tid >> 5;
    const int wm = wid & 3, wn = wid >> 2;
    const int qr = lane >> 2, qc = lane & 3;

    for (;;){
        if (tid == 0) s_tile = atomicAdd(&g_work, 1u);
        __syncthreads();
        unsigned n = s_tile;
        if (n >= (unsigned)TOTAL_TILES) break;
        __syncthreads();                  // protect s_tile before next overwrite
        const int t   = (int)(n >> 6);
        const int sub = (int)(n & 63);
        const int b0  = (sub >> 5) * BM;
        const int n0  = (sub & 31) * BN;

        float acc[2][2][4];
        #pragma unroll
        for (int mm=0;mm<2;mm++)
            #pragma unroll
            for (int nn=0;nn<2;nn++)
                #pragma unroll
                for (int i=0;i<4;i++) acc[mm][nn][i]=0.f;

        for (int kt = 0; kt < KX/BK; kt++){
            int k0 = kt * BK;
            #pragma unroll
            for (int i = 0; i < 2; i++){
                int idx = tid + i*512;
                int row = idx >> 3, c4 = (idx & 7) * 4;
                int b  = b0 + row;
                int kg = k0 + c4;
                float4 v;
                if (kg < Fn){
                    if (t == 0) v = make_float4(0.f,0.f,0.f,0.f);
                    else v = *reinterpret_cast<const float4*>(
                                teacher + ((size_t)b*Tn + (t-1))*Fn + kg);
                } else {
                    v = *reinterpret_cast<const float4*>(
                                cond + ((size_t)b*Tn + t)*CUn + (kg - Fn));
                }
                st4_tf(As + row*ASTR + c4, v);
            }
            {
                int kr = tid >> 4, c4 = (tid & 15) * 4;
                float4 v = *reinterpret_cast<const float4*>(
                               W + (size_t)(k0+kr)*NG + n0 + c4);
                st4_tf(Bs + kr*BSTR + c4, v);
            }
            __syncthreads();
            #pragma unroll
            for (int k8 = 0; k8 < BK; k8 += 8){
                uint32_t a[2][4];
                #pragma unroll
                for (int mm = 0; mm < 2; mm++){
                    const float* ap = As + (wm*32 + mm*16 + qr) * ASTR + k8 + qc;
                    a[mm][0] = __float_as_uint(ap[0]);
                    a[mm][1] = __float_as_uint(ap[8*ASTR]);
                    a[mm][2] = __float_as_uint(ap[4]);
                    a[mm][3] = __float_as_uint(ap[8*ASTR + 4]);
                }
                #pragma unroll
                for (int nn = 0; nn < 2; nn++){
                    const float* bp = Bs + (k8 + qc) * BSTR + wn*16 + nn*8 + qr;
                    uint32_t b0r = __float_as_uint(bp[0]);
                    uint32_t b1r = __float_as_uint(bp[4*BSTR]);
                    #pragma unroll
                    for (int mm = 0; mm < 2; mm++)
                        mma_tf32(acc[mm][nn], a[mm][0], a[mm][1], a[mm][2], a[mm][3],
                                 b0r, b1r);
                }
            }
            __syncthreads();
        }

        // epilogue: write tile to g_Zpre
        const size_t r0 = (size_t)t*Bn + b0;
        #pragma unroll
        for (int mm=0;mm<2;mm++){
            int row = wm*32 + mm*16 + qr;
            #pragma unroll
            for (int nn=0;nn<2;nn++){
                int col = n0 + wn*16 + nn*8 + qc*2;
                float bv0 = bias[col], bv1 = bias[col+1];
                float* z0 = g_Zpre + (r0 + row) * NG + col;
                z0[0] = acc[mm][nn][0] + bv0;
                z0[1] = acc[mm][nn][1] + bv1;
                float* z1 = g_Zpre + (r0 + row + 8) * NG + col;
                z1[0] = acc[mm][nn][2] + bv0;
                z1[1] = acc[mm][nn][3] + bv1;
            }
        }
        __threadfence();              // each thread's stores gpu-visible
        __syncthreads();
        if (tid == 0) atomicAdd(&g_zdone[t], 1u);   // fence-before-add = release
    }
}

__global__ __launch_bounds__(512) void k_fused(const float* __restrict__ teacher,
                                               const float* __restrict__ cond,
                                               const float* __restrict__ W,
                                               const float* __restrict__ bias,
                                               const float* __restrict__ U,
                                               const float* __restrict__ c0,
                                               float* __restrict__ out){
    extern __shared__ float sm[];
    if (blockIdx.x < NREC)
        consumer_role(U, c0, out, sm);
    else
        producer_role(teacher, cond, W, bias, sm);
}

// ===========================================================================
// k_out: out[b,t,f] = sigmoid(H @ Wo + bo)
// ===========================================================================
__device__ __forceinline__ void compute_ktile(const float* As, const float* Bs,
                                              float acc[2][4][4], int wm, int wn, int lane){
    const int qr = lane >> 2, qc = lane & 3;
    #pragma unroll
    for (int k8 = 0; k8 < BK; k8 += 8){
        uint32_t a[2][4];
        #pragma unroll
        for (int mm = 0; mm < 2; mm++){
            const float* ap = As + (wm*32 + mm*16 + qr) * ASTR + k8 + qc;
            a[mm][0] = __float_as_uint(ap[0]);
            a[mm][1] = __float_as_uint(ap[8*ASTR]);
            a[mm][2] = __float_as_uint(ap[4]);
            a[mm][3] = __float_as_uint(ap[8*ASTR + 4]);
        }
        #pragma unroll
        for (int nn = 0; nn < 4; nn++){
            const float* bp = Bs + (k8 + qc) * BSTR + wn*32 + nn*8 + qr;
            uint32_t b0 = __float_as_uint(bp[0]);
            uint32_t b1 = __float_as_uint(bp[4*BSTR]);
            #pragma unroll
            for (int mm = 0; mm < 2; mm++)
                mma_tf32(acc[mm][nn], a[mm][0], a[mm][1], a[mm][2], a[mm][3], b0, b1);
        }
    }
}

__global__ __launch_bounds__(256) void k_out(const float* __restrict__ Wo,
                                             const float* __restrict__ bo,
                                             float* __restrict__ out){
    __shared__ float As[BM*ASTR];
    __shared__ float Bs[BK*BSTR];
    const int tid = threadIdx.x, lane = tid & 31, wid = tid >> 5;
    const int wm = wid & 3, wn = wid >> 2;
    const int f0 = blockIdx.x * BN;
    const int r0 = blockIdx.y * BM;

    float acc[2][4][4];
    #pragma unroll
    for (int mm=0;mm<2;mm++)
        #pragma unroll
        for (int nn=0;nn<4;nn++)
            #pragma unroll
            for (int i=0;i<4;i++) acc[mm][nn][i]=0.f;

    for (int kt = 0; kt < DUn/BK; kt++){
        int k0 = kt * BK;
        #pragma unroll
        for (int i = 0; i < 4; i++){
            int idx = tid + i*256;
            int row = idx >> 3, c4 = (idx & 7) * 4;
            float4 v = *reinterpret_cast<const float4*>(
                            g_H + (size_t)(r0+row)*DUn + k0 + c4);
            st4_tf(As + row*ASTR + c4, v);
        }
        #pragma unroll
        for (int i = 0; i < 2; i++){
            int idx = tid + i*256;
            int kr = idx >> 4, c4 = (idx & 15) * 4;
            float4 v = *reinterpret_cast<const float4*>(
                            Wo + (size_t)(k0+kr)*Fn + f0 + c4);
            st4_tf(Bs + kr*BSTR + c4, v);
        }
        __syncthreads();
        compute_ktile(As, Bs, acc, wm, wn, lane);
        __syncthreads();
    }

    const int qr = lane >> 2, qc = lane & 3;
    #pragma unroll
    for (int mm=0;mm<2;mm++){
        int r = r0 + wm*32 + mm*16 + qr;
        #pragma unroll
        for (int nn=0;nn<4;nn++){
            int f = f0 + wn*32 + nn*8 + qc*2;
            float bv0 = bo[f], bv1 = bo[f+1];
            {
                int b = r & (Bn-1), tt = r >> 8;
                float* o = out + ((size_t)b*Tn + tt)*Fn + f;
                o[0] = sigm(acc[mm][nn][0] + bv0);
                o[1] = sigm(acc[mm][nn][1] + bv1);
            }
            {
                int r2 = r + 8;
                int b = r2 & (Bn-1), tt = r2 >> 8;
                float* o = out + ((size_t)b*Tn + tt)*Fn + f;
                o[0] = sigm(acc[mm][nn][2] + bv0);
                o[1] = sigm(acc[mm][nn][3] + bv1);
            }
        }
    }
}

__global__ void k_init(const float* __restrict__ h0){
    int i = blockIdx.x * blockDim.x + threadIdx.x;
    if (i == 0){ g_bar = 0u; g_work = 0u; }
    if (i < Tn) g_zdone[i] = 0u;
    g_h0r[i] = tf2f(f2tf(h0[i]));
}

extern "C" void kernel_launch(void* const* d_in, const int* in_sizes, int n_in,
                              void* d_out, int out_size){
    (void)in_sizes; (void)n_in; (void)out_size;
    const float* conductor = (const float*)d_in[0];
    const float* teacher   = (const float*)d_in[1];
    const float* h0   = (const float*)d_in[2];
    const float* c0   = (const float*)d_in[3];
    const float* W    = (const float*)d_in[4];
    const float* U    = (const float*)d_in[5];
    const float* bias = (const float*)d_in[6];
    const float* Wo   = (const float*)d_in[7];
    const float* bo   = (const float*)d_in[8];
    float* out = (float*)d_out;

    cudaFuncSetAttribute(k_fused, cudaFuncAttributeMaxDynamicSharedMemorySize,
                         SM_FLOATS * (int)sizeof(float));

    k_init<<<(Bn*DUn)/256, 256>>>(h0);
    k_fused<<<NCTA_ALL, 512, SM_FLOATS * sizeof(float)>>>(
        teacher, conductor, W, bias, U, c0, out);
    k_out<<<dim3(Fn/BN, Rn/BM), 256>>>(Wo, bo, out);
}